// round 8
// baseline (speedup 1.0000x reference)
#include <cuda_runtime.h>
#include <cuda_fp16.h>
#include <mma.h>
#include <cstdint>

using namespace nvcuda;

#define HID     128
#define M_TILE  64
#define THREADS 256
#define LDH     136     // half stride: 272B ≡ 16 mod 128 -> conflict-free LDSM

// Scratch: per-node aggregate. Zero at module load; mlp re-zeroes after
// reading so the invariant holds across CUDA-graph replays.
__device__ float g_agg[65536];

__device__ __forceinline__ float silu(float x) {
    return x * (1.0f / (1.0f + __expf(-x)));
}

// ---------------------------------------------------------------------------
// scatter-add distances into g_agg[row[e]], 4 edges per thread.
// Edge dtype probed: jax randint int64 silently demotes to int32 when x64 is
// off; true int64 buffers have all-zero high words (indices < 50000).
// ---------------------------------------------------------------------------
__global__ void scatter_kernel(const int* __restrict__ edges_i32,
                               const float* __restrict__ dist, int E) {
    __shared__ int sstride;
    if (threadIdx.x == 0) {
        bool all_zero = true;
        int probe = E < 16 ? E : 16;
        for (int j = 0; j < probe; j++)
            if (edges_i32[2 * j + 1] != 0) { all_zero = false; break; }
        sstride = all_zero ? 2 : 1;
    }
    __syncthreads();
    int stride = sstride;
    int i4 = (blockIdx.x * blockDim.x + threadIdx.x) * 4;
    if (i4 + 3 < E) {
        float4 d = __ldg((const float4*)&dist[i4]);
        int r0, r1, r2, r3;
        if (stride == 1) {
            int4 r = __ldg((const int4*)&edges_i32[i4]);
            r0 = r.x; r1 = r.y; r2 = r.z; r3 = r.w;
        } else {
            int4 ra = __ldg((const int4*)&edges_i32[2 * i4]);
            int4 rb = __ldg((const int4*)&edges_i32[2 * i4 + 4]);
            r0 = ra.x; r1 = ra.z; r2 = rb.x; r3 = rb.z;
        }
        atomicAdd(&g_agg[r0], d.x);
        atomicAdd(&g_agg[r1], d.y);
        atomicAdd(&g_agg[r2], d.z);
        atomicAdd(&g_agg[r3], d.w);
    } else {
        for (int j = i4; j < E; j++) {
            int r = edges_i32[(long long)j * stride];
            atomicAdd(&g_agg[r], dist[j]);
        }
    }
}

using FragA = wmma::fragment<wmma::matrix_a, 16, 16, 16, __half, wmma::row_major>;
using FragB = wmma::fragment<wmma::matrix_b, 16, 16, 16, __half, wmma::row_major>;
using FragC = wmma::fragment<wmma::accumulator, 16, 16, 16, float>;

// acc[2][2] += A[r0..+31][0..127] @ B[0..127][c0..+31], fp16 smem, ping-pong.
__device__ __forceinline__ void gemm_fp16(const __half* __restrict__ as,
                                          const __half* __restrict__ bs,
                                          int r0, int c0, FragC acc[2][2]) {
    FragA af[2][2];
    FragB bf[2][2];
    wmma::load_matrix_sync(af[0][0], as + (size_t)r0 * LDH, LDH);
    wmma::load_matrix_sync(af[0][1], as + (size_t)(r0 + 16) * LDH, LDH);
    wmma::load_matrix_sync(bf[0][0], bs + c0, LDH);
    wmma::load_matrix_sync(bf[0][1], bs + c0 + 16, LDH);
#pragma unroll
    for (int ks = 0; ks < 8; ks++) {
        int cur = ks & 1, nxt = cur ^ 1;
        if (ks < 7) {
            int k = (ks + 1) * 16;
            wmma::load_matrix_sync(af[nxt][0], as + (size_t)r0 * LDH + k, LDH);
            wmma::load_matrix_sync(af[nxt][1], as + (size_t)(r0 + 16) * LDH + k, LDH);
            wmma::load_matrix_sync(bf[nxt][0], bs + (size_t)k * LDH + c0, LDH);
            wmma::load_matrix_sync(bf[nxt][1], bs + (size_t)k * LDH + c0 + 16, LDH);
        }
#pragma unroll
        for (int i = 0; i < 2; i++)
#pragma unroll
            for (int j = 0; j < 2; j++)
                wmma::mma_sync(acc[i][j], af[cur][i], bf[cur][j], acc[i][j]);
    }
}

// ---------------------------------------------------------------------------
// smem layout (bytes), per CTA — sized so 2 CTAs co-reside per SM
// ---------------------------------------------------------------------------
#define SM_W1H   0                      // half[128*LDH] 34816
#define SM_W2H   34816
#define SM_XH    69632                  // half[64*LDH]  17408
#define SM_TH    87040                  // half[64*LDH]  17408
#define SM_W1R   104448                 // f32[128]
#define SM_B1    104960
#define SM_B2    105472
#define SM_AGG   105984                 // f32[64]
#define SM_IOTA  106240                 // f32[256]
#define SM_TOTAL 107264

// ---------------------------------------------------------------------------
// Fused node MLP (fp16 TC, fp32 accum), 2 CTAs/SM for phase overlap:
//   t = silu(h@W1[:128] + agg*W1[128] + b1);  out = h + t@W2 + b2
// M_TILE=64, 8 warps, warp tile 32x32 (2 row-groups x 4 col-groups).
// ---------------------------------------------------------------------------
__global__ void __launch_bounds__(THREADS, 2)
mlp_kernel(const float* __restrict__ h,
           const float* __restrict__ W1, const float* __restrict__ b1,
           const float* __restrict__ W2, const float* __restrict__ b2,
           float* __restrict__ out, int n_nodes, int n_tiles)
{
    extern __shared__ char sm[];
    __half* w1h  = (__half*)(sm + SM_W1H);
    __half* w2h  = (__half*)(sm + SM_W2H);
    __half* xh   = (__half*)(sm + SM_XH);
    __half* th   = (__half*)(sm + SM_TH);
    float*  w1r  = (float*)(sm + SM_W1R);
    float*  b1s  = (float*)(sm + SM_B1);
    float*  b2s  = (float*)(sm + SM_B2);
    float*  sagg = (float*)(sm + SM_AGG);
    float*  iota = (float*)(sm + SM_IOTA);

    const int tid  = threadIdx.x;
    const int warp = tid >> 5;
    const int r0   = (warp >> 2) * 32;   // 0 or 32
    const int c0   = (warp & 3) * 32;    // 0,32,64,96

    // ---- stage weights (fp16) + vectors (fp32) once per CTA ----
    for (int idx = tid; idx < 128 * 32; idx += THREADS) {
        int k = idx >> 5, c4 = (idx & 31) << 2;
        float4 v1 = __ldg((const float4*)&W1[k * HID + c4]);
        float4 v2 = __ldg((const float4*)&W2[k * HID + c4]);
        __half2 p0 = __floats2half2_rn(v1.x, v1.y);
        __half2 p1 = __floats2half2_rn(v1.z, v1.w);
        __half2 q0 = __floats2half2_rn(v2.x, v2.y);
        __half2 q1 = __floats2half2_rn(v2.z, v2.w);
        uint2 pk, qk;
        pk.x = *reinterpret_cast<unsigned*>(&p0);
        pk.y = *reinterpret_cast<unsigned*>(&p1);
        qk.x = *reinterpret_cast<unsigned*>(&q0);
        qk.y = *reinterpret_cast<unsigned*>(&q1);
        *reinterpret_cast<uint2*>(&w1h[(size_t)k * LDH + c4]) = pk;
        *reinterpret_cast<uint2*>(&w2h[(size_t)k * LDH + c4]) = qk;
    }
    if (tid < 32) {
        *(float4*)&w1r[tid * 4] = __ldg((const float4*)&W1[128 * HID + tid * 4]);
        *(float4*)&b1s[tid * 4] = __ldg((const float4*)&b1[tid * 4]);
        *(float4*)&b2s[tid * 4] = __ldg((const float4*)&b2[tid * 4]);
    }
    if (tid < 256) iota[tid] = (float)tid;
    __syncthreads();

    // decode accumulator fragment layout once (layout-agnostic)
    int dr[FragC::num_elements], dc[FragC::num_elements];
    {
        FragC idxf;
        wmma::load_matrix_sync(idxf, iota, 16, wmma::mem_row_major);
#pragma unroll
        for (int e = 0; e < idxf.num_elements; e++) {
            int v = __float2int_rn(idxf.x[e]);
            dr[e] = v >> 4;
            dc[e] = v & 15;
        }
    }

    for (int tile = blockIdx.x; tile < n_tiles; tile += gridDim.x) {
        const int base = tile * M_TILE;
        const bool full = (base + M_TILE <= n_nodes);
        __syncthreads();   // prev tile fully consumed (xh/th reads done)

        // ---- fill X (fp16) + agg slice (fp32), re-zero g_agg ----
#pragma unroll
        for (int t = 0; t < 8; t++) {
            int idx = tid + t * THREADS;          // 0..2047
            int m = idx >> 5, c4 = (idx & 31) << 2;
            int gn = base + m;
            float4 v = make_float4(0.f, 0.f, 0.f, 0.f);
            if (gn < n_nodes) v = __ldg((const float4*)&h[(size_t)gn * HID + c4]);
            __half2 p0 = __floats2half2_rn(v.x, v.y);
            __half2 p1 = __floats2half2_rn(v.z, v.w);
            uint2 pk;
            pk.x = *reinterpret_cast<unsigned*>(&p0);
            pk.y = *reinterpret_cast<unsigned*>(&p1);
            *reinterpret_cast<uint2*>(&xh[(size_t)m * LDH + c4]) = pk;
        }
        if (tid < M_TILE) {
            int gn = base + tid;
            float a = 0.f;
            if (gn < n_nodes) { a = g_agg[gn] * 0.01f; g_agg[gn] = 0.f; }
            sagg[tid] = a;
        }
        __syncthreads();

        // ---- GEMM1: D1 = X @ W1[:128] ----
        FragC acc[2][2];
#pragma unroll
        for (int i = 0; i < 2; i++)
#pragma unroll
            for (int j = 0; j < 2; j++) wmma::fill_fragment(acc[i][j], 0.0f);
        gemm_fp16(xh, w1h, r0, c0, acc);

        // ---- epilogue1 (fp32 regs): t = silu(D1 + agg[r]*w1r[c] + b1[c]) ----
#pragma unroll
        for (int i = 0; i < 2; i++)
#pragma unroll
            for (int j = 0; j < 2; j++)
#pragma unroll
                for (int e = 0; e < FragC::num_elements; e++) {
                    int r = r0 + i * 16 + dr[e];
                    int c = c0 + j * 16 + dc[e];
                    float v = acc[i][j].x[e] + sagg[r] * w1r[c] + b1s[c];
                    th[(size_t)r * LDH + c] = __float2half_rn(silu(v));
                }

        // ---- residual preload into acc2 (gmem fp32) ----
        FragC acc2[2][2];
        if (full) {
#pragma unroll
            for (int i = 0; i < 2; i++)
#pragma unroll
                for (int j = 0; j < 2; j++)
                    wmma::load_matrix_sync(acc2[i][j],
                        &h[(size_t)(base + r0 + i * 16) * HID + c0 + j * 16],
                        HID, wmma::mem_row_major);
        } else {
#pragma unroll
            for (int i = 0; i < 2; i++)
#pragma unroll
                for (int j = 0; j < 2; j++) wmma::fill_fragment(acc2[i][j], 0.0f);
        }
        __syncthreads();   // th complete before GEMM2 reads

        // ---- GEMM2: out = residual + T @ W2 + b2 ----
        gemm_fp16(th, w2h, r0, c0, acc2);

        if (full) {
#pragma unroll
            for (int i = 0; i < 2; i++)
#pragma unroll
                for (int j = 0; j < 2; j++) {
#pragma unroll
                    for (int e = 0; e < FragC::num_elements; e++)
                        acc2[i][j].x[e] += b2s[c0 + j * 16 + dc[e]];
                    wmma::store_matrix_sync(
                        &out[(size_t)(base + r0 + i * 16) * HID + c0 + j * 16],
                        acc2[i][j], HID, wmma::mem_row_major);
                }
        } else {
            // partial last tile: guarded scalar stores with residual
#pragma unroll
            for (int i = 0; i < 2; i++)
#pragma unroll
                for (int j = 0; j < 2; j++)
#pragma unroll
                    for (int e = 0; e < FragC::num_elements; e++) {
                        int gn = base + r0 + i * 16 + dr[e];
                        int c  = c0 + j * 16 + dc[e];
                        if (gn < n_nodes)
                            out[(size_t)gn * HID + c] =
                                __ldg(&h[(size_t)gn * HID + c]) +
                                acc2[i][j].x[e] + b2s[c];
                    }
        }
    }
}

// ---------------------------------------------------------------------------
extern "C" void kernel_launch(void* const* d_in, const int* in_sizes, int n_in,
                              void* d_out, int out_size) {
    const float* h    = (const float*)d_in[0];
    const int*   edg  = (const int*)  d_in[1];
    const float* dist = (const float*)d_in[2];
    const float* W1   = (const float*)d_in[9];   // W_n1 [129,128]
    const float* b1   = (const float*)d_in[10];
    const float* W2   = (const float*)d_in[11];  // W_n2 [128,128]
    const float* b2   = (const float*)d_in[12];
    float* out = (float*)d_out;

    int n_nodes = in_sizes[0] / HID;
    int E       = in_sizes[2];

    int sblocks = ((E + 3) / 4 + 255) / 256;
    scatter_kernel<<<sblocks, 256>>>(edg, dist, E);

    cudaFuncSetAttribute(mlp_kernel,
                         cudaFuncAttributeMaxDynamicSharedMemorySize, SM_TOTAL);
    int sms = 148;
    cudaDeviceGetAttribute(&sms, cudaDevAttrMultiProcessorCount, 0);
    int n_tiles = (n_nodes + M_TILE - 1) / M_TILE;
    int grid = n_tiles < 2 * sms ? n_tiles : 2 * sms;
    mlp_kernel<<<grid, THREADS, SM_TOTAL>>>(h, W1, b1, W2, b2, out,
                                            n_nodes, n_tiles);
}